// round 15
// baseline (speedup 1.0000x reference)
#include <cuda_runtime.h>

// SparseScatter: y = y_base with 4096 active 16x16x32 tiles overwritten by
// transposed x blocks (x is [a, C, 16, 16] -> output NHWC).
//
// R15: persistent grid-stride CTAs. 740 CTAs (148 SMs x 5 resident, the
//   register-limited residency: 48 regs x 1536 thr > 64K RF), each looping
//   ~11 tiles. Collapses ~11 CTA waves into 1: no per-CTA drain/ramp MLP
//   bubbles, no (n_waves-1)*T_wave_trans. Per-tile body is byte-identical
//   to the proven R8/R14 body (main 78.3us, DRAM 77.9%). New __syncthreads
//   at top of active branch = WAR guard for xs reuse across iterations
//   (branch is CTA-uniform: a is per-tile).
//
//   Falsified levers (do not revisit): reg-capped occupancy (R7: kills
//   per-warp MLP, DRAM 78->61), SMEM halving (R6: reg bloat), prologue
//   restructuring (R5/R6/R8/R9: total-invariant).
//
// Shapes fixed by reference: x (4096,32,16,16) f32; y_base (8,512,512,32) f32;
// indices (4096,3) i32; bh=bw=sh=sw=16, oh=ow=0.
// DRAM floor = 256MB write + 128MB x + 128MB inactive y_base = 512MB.

#define Bn   8
#define Hh   512
#define Ww   512
#define Cc   32
#define GH   32
#define GW   32
#define NBLK (Bn*GH*GW)   // 8192
#define NACT 4096
#define PGRID 740         // 148 SMs x 5 resident CTAs

__device__ int g_map[NBLK];

__global__ void __launch_bounds__(1024)
fill_map_k(const int* __restrict__ idx) {
    int a = blockIdx.x * 1024 + threadIdx.x;   // 4 CTAs x 1024 = 4096
    int n  = idx[3*a + 0];
    int yb = idx[3*a + 1];
    int xb = idx[3*a + 2];
    g_map[(n * GH + yb) * GW + xb] = a;
}

// Persistent CTAs: each processes tiles bid = blockIdx.x, +PGRID, ...
// Tile = 16x16x32 = 2048 float4; 256 threads x 8 float4 each.
__global__ void __launch_bounds__(256)
scatter_main_k(const float* __restrict__ x,
               const float4* __restrict__ yb4,
               float4* __restrict__ out4) {
    __shared__ float xs[Cc * 257];   // 33KB; stride 257 ≡ 1 mod 32 -> conflict-free

    int t = threadIdx.x;
    const int rs4 = Ww * (Cc / 4);   // 4096 float4 per output row

    for (int bid = blockIdx.x; bid < NBLK; bid += PGRID) {
        int a  = g_map[bid];

        int xb = bid & 31;
        int yb = (bid >> 5) & 31;
        int n  = bid >> 10;

        int rowbase0 = (n * Hh * Ww + (yb << 4) * Ww + (xb << 4)) * (Cc / 4);

        if (a < 0) {
            // pass-through copy, fully coalesced float4, loads front-batched
            float4 v[8];
            int    o[8];
            #pragma unroll
            for (int k = 0; k < 8; k++) {
                int p   = (k << 8) + t;
                int i   = p >> 7;
                int rem = p & 127;
                o[k] = rowbase0 + i * rs4 + rem;
                v[k] = __ldcs(&yb4[o[k]]);
            }
            #pragma unroll
            for (int k = 0; k < 8; k++) __stcs(&out4[o[k]], v[k]);
        } else {
            // WAR guard: all warps done reading xs from any previous active
            // tile before restaging. Branch is CTA-uniform (a is per-tile).
            __syncthreads();

            // Stage x block through SMEM (transpose): x[a][ch][pos],
            // pos=i*16+j. Load: ch=m, pos=t, coalesced; STS bank=(m+t)%32
            // conflict-free. Read: banks 4*(rem&7)+(rem>>3)+c cover all 32.
            const float* xblk = x + (long)a * (Cc * 256);
            #pragma unroll
            for (int m = 0; m < Cc; m++)
                xs[m * 257 + t] = __ldcs(&xblk[m * 256 + t]);
            __syncthreads();

            #pragma unroll
            for (int k = 0; k < 8; k++) {
                int p   = (k << 8) + t;
                int i   = p >> 7;
                int rem = p & 127;
                int j   = rem >> 3;
                int ch  = (rem & 7) << 2;
                int pos = (i << 4) + j;
                float4 v;
                v.x = xs[(ch + 0) * 257 + pos];
                v.y = xs[(ch + 1) * 257 + pos];
                v.z = xs[(ch + 2) * 257 + pos];
                v.w = xs[(ch + 3) * 257 + pos];
                __stcs(&out4[rowbase0 + i * rs4 + rem], v);
            }
        }
    }
}

extern "C" void kernel_launch(void* const* d_in, const int* in_sizes, int n_in,
                              void* d_out, int out_size) {
    const float* x      = nullptr;
    const float* y_base = nullptr;
    const int*   idx    = nullptr;

    for (int i = 0; i < n_in; i++) {
        if (in_sizes[i] == 33554432)      x      = (const float*)d_in[i];
        else if (in_sizes[i] == 67108864) y_base = (const float*)d_in[i];
        else if (in_sizes[i] == 12288)    idx    = (const int*)d_in[i];
    }

    // Clear map to -1 via memset node (0xFF bytes), then parallel fill.
    void* map_ptr = nullptr;
    cudaGetSymbolAddress(&map_ptr, g_map);
    cudaMemsetAsync(map_ptr, 0xFF, NBLK * sizeof(int));

    fill_map_k<<<NACT / 1024, 1024>>>(idx);
    scatter_main_k<<<PGRID, 256>>>(x, (const float4*)y_base, (float4*)d_out);
}

// round 16
// speedup vs baseline: 1.1080x; 1.1080x over previous
#include <cuda_runtime.h>

// SparseScatter: y = y_base with 4096 active 16x16x32 tiles overwritten by
// transposed x blocks (x is [a, C, 16, 16] -> output NHWC).
//
// R16 = R14 body (proven: main 77.7-78.3us, DRAM ~78%, total 87.6) with ONE
//   local change: position-major SMEM (stride 36 words) so the transpose
//   read is a single LDS.128 instead of 4x LDS.32, and staging uses STS.128.
//   Bank proofs: STS.128 lane l -> word l*36+m, 36l≡4l (mod 32), phase of 8
//   lanes covers banks {4l..4l+3} = all 32. LDS.128: 8 lanes read words
//   pos*36+{0..31} = all 32 banks. Both conflict-free; 36≡0 mod 4 keeps
//   16B alignment. Copy path untouched (8-deep float4 batch, free regs).
//
//   Dead levers (falsified, do not revisit): reg-capped occupancy (R7),
//   SMEM halving (R6), prologue restructuring (R5/6/8/9), persistent
//   grid-stride (R15: reg union 48->80, occ 32%, DRAM 72%).
//
// Shapes fixed by reference: x (4096,32,16,16) f32; y_base (8,512,512,32) f32;
// indices (4096,3) i32; bh=bw=sh=sw=16, oh=ow=0.
// DRAM floor = 256MB write + 128MB x + 128MB inactive y_base = 512MB.

#define Bn   8
#define Hh   512
#define Ww   512
#define Cc   32
#define GH   32
#define GW   32
#define NBLK (Bn*GH*GW)   // 8192
#define NACT 4096

__device__ int g_map[NBLK];

__global__ void __launch_bounds__(1024)
fill_map_k(const int* __restrict__ idx) {
    int a = blockIdx.x * 1024 + threadIdx.x;   // 4 CTAs x 1024 = 4096
    int n  = idx[3*a + 0];
    int yb = idx[3*a + 1];
    int xb = idx[3*a + 2];
    g_map[(n * GH + yb) * GW + xb] = a;
}

// One CTA per 16x16x32 tile (8192 CTAs), 256 threads, 2048 float4 per tile.
__global__ void __launch_bounds__(256)
scatter_main_k(const float* __restrict__ x,
               const float4* __restrict__ yb4,
               float4* __restrict__ out4) {
    // Position-major: xs[pos*36 + ch], pos 0..255, ch 0..31 (+4 pad words).
    __shared__ float xs[256 * 36];   // 36KB; 6 CTAs/SM by SMEM, 5 by regs

    int bid = blockIdx.x;
    int a   = g_map[bid];

    int xb = bid & 31;
    int yb = (bid >> 5) & 31;
    int n  = bid >> 10;
    int t  = threadIdx.x;

    int rowbase0 = (n * Hh * Ww + (yb << 4) * Ww + (xb << 4)) * (Cc / 4);
    const int rs4 = Ww * (Cc / 4);   // 4096 float4 per output row

    if (a < 0) {
        // pass-through copy, fully coalesced float4, loads front-batched
        float4 v[8];
        int    o[8];
        #pragma unroll
        for (int k = 0; k < 8; k++) {
            int p   = (k << 8) + t;
            int i   = p >> 7;
            int rem = p & 127;
            o[k] = rowbase0 + i * rs4 + rem;
            v[k] = __ldcs(&yb4[o[k]]);
        }
        #pragma unroll
        for (int k = 0; k < 8; k++) __stcs(&out4[o[k]], v[k]);
    } else {
        // Stage x block transposed: thread t = position, gathers 4 channels
        // per iteration (coalesced LDG per channel plane), one STS.128.
        const float* xblk = x + (long)a * (Cc * 256);
        float4* xsv = reinterpret_cast<float4*>(xs);
        #pragma unroll
        for (int m = 0; m < Cc; m += 4) {
            float4 w;
            w.x = __ldcs(&xblk[(m + 0) * 256 + t]);
            w.y = __ldcs(&xblk[(m + 1) * 256 + t]);
            w.z = __ldcs(&xblk[(m + 2) * 256 + t]);
            w.w = __ldcs(&xblk[(m + 3) * 256 + t]);
            xsv[t * 9 + (m >> 2)] = w;    // word addr t*36 + m, 16B aligned
        }
        __syncthreads();

        // Read: one LDS.128 per output float4; 8-lane phase covers all banks.
        #pragma unroll
        for (int k = 0; k < 8; k++) {
            int p   = (k << 8) + t;
            int i   = p >> 7;
            int rem = p & 127;
            int j   = rem >> 3;
            int chq = rem & 7;            // channel quad 0..7
            int pos = (i << 4) + j;
            float4 v = xsv[pos * 9 + chq];
            __stcs(&out4[rowbase0 + i * rs4 + rem], v);
        }
    }
}

extern "C" void kernel_launch(void* const* d_in, const int* in_sizes, int n_in,
                              void* d_out, int out_size) {
    const float* x      = nullptr;
    const float* y_base = nullptr;
    const int*   idx    = nullptr;

    for (int i = 0; i < n_in; i++) {
        if (in_sizes[i] == 33554432)      x      = (const float*)d_in[i];
        else if (in_sizes[i] == 67108864) y_base = (const float*)d_in[i];
        else if (in_sizes[i] == 12288)    idx    = (const int*)d_in[i];
    }

    // Clear map to -1 via memset node (0xFF bytes), then parallel fill.
    void* map_ptr = nullptr;
    cudaGetSymbolAddress(&map_ptr, g_map);
    cudaMemsetAsync(map_ptr, 0xFF, NBLK * sizeof(int));

    fill_map_k<<<NACT / 1024, 1024>>>(idx);
    scatter_main_k<<<NBLK, 256>>>(x, (const float4*)y_base, (float4*)d_out);
}